// round 5
// baseline (speedup 1.0000x reference)
#include <cuda_runtime.h>

#define TPB 256          // 8 warps/CTA
#define NBLOCKS 1184     // 148 SMs * 8 resident CTAs (warp-limited)

// cov = (R * colscale) @ (R * colscale)^T per point.
// scaling_raw [N,3] fp32, rotation_raw [N,4] fp32 (w,x,y,z), out [N,3,3] fp32.
__global__ __launch_bounds__(TPB) void cov_kernel(
    const float* __restrict__ s_raw,
    const float4* __restrict__ q_raw,
    float* __restrict__ out,
    int n)
{
    __shared__ float sh_s[TPB * 3];   // 3 KB per-warp-sliced scaling stage
    __shared__ float sh_o[TPB * 9];   // 9 KB per-warp-sliced output stage

    const int ntiles_full = n / TPB;
    const int warp = threadIdx.x >> 5;
    const int lane = threadIdx.x & 31;
    const float4* s4g = reinterpret_cast<const float4*>(s_raw);
    float4* s4s = reinterpret_cast<float4*>(sh_s);
    const float4* s4o = reinterpret_cast<const float4*>(sh_o);

    int tile = blockIdx.x;

    // ---- prefetch first tile ----
    float4 q, sv;
    if (tile < ntiles_full) {
        q = q_raw[(size_t)tile * TPB + threadIdx.x];
        if (lane < 24)
            sv = s4g[(size_t)tile * (TPB * 3 / 4) + warp * 24 + lane];
    }

    while (tile < ntiles_full) {
        const int next = tile + NBLOCKS;

        // stage current scaling into this warp's smem slice
        if (lane < 24) s4s[warp * 24 + lane] = sv;
        __syncwarp();

        // ---- prefetch next tile (loads in flight under compute+store) ----
        float4 qn, svn;
        if (next < ntiles_full) {
            qn = q_raw[(size_t)next * TPB + threadIdx.x];
            if (lane < 24)
                svn = s4g[(size_t)next * (TPB * 3 / 4) + warp * 24 + lane];
        }

        // ---- compute ----
        {
            const float n2 = q.x * q.x + q.y * q.y + q.z * q.z + q.w * q.w;
            const float inv = rsqrtf(fmaxf(n2, 1e-24f));
            const float w = q.x * inv, x = q.y * inv, y = q.z * inv, z = q.w * inv;

            const float sx = __expf(sh_s[threadIdx.x * 3 + 0]);
            const float sy = __expf(sh_s[threadIdx.x * 3 + 1]);
            const float sz = __expf(sh_s[threadIdx.x * 3 + 2]);

            const float m00 = (1.f - 2.f * (y * y + z * z)) * sx;
            const float m01 = (2.f * (x * y - w * z)) * sy;
            const float m02 = (2.f * (x * z + w * y)) * sz;
            const float m10 = (2.f * (x * y + w * z)) * sx;
            const float m11 = (1.f - 2.f * (x * x + z * z)) * sy;
            const float m12 = (2.f * (y * z - w * x)) * sz;
            const float m20 = (2.f * (x * z - w * y)) * sx;
            const float m21 = (2.f * (y * z + w * x)) * sy;
            const float m22 = (1.f - 2.f * (x * x + y * y)) * sz;

            const float c00 = m00 * m00 + m01 * m01 + m02 * m02;
            const float c01 = m00 * m10 + m01 * m11 + m02 * m12;
            const float c02 = m00 * m20 + m01 * m21 + m02 * m22;
            const float c11 = m10 * m10 + m11 * m11 + m12 * m12;
            const float c12 = m10 * m20 + m11 * m21 + m12 * m22;
            const float c22 = m20 * m20 + m21 * m21 + m22 * m22;

            // stride-9 smem writes: gcd(9,32)=1 -> conflict-free
            float* o = &sh_o[threadIdx.x * 9];
            o[0] = c00; o[1] = c01; o[2] = c02;
            o[3] = c01; o[4] = c11; o[5] = c12;
            o[6] = c02; o[7] = c12; o[8] = c22;
        }
        __syncwarp();

        // ---- per-warp vectorized store: 72 float4s per warp ----
        {
            float4* g4 = reinterpret_cast<float4*>(out) +
                         (size_t)tile * (TPB * 9 / 4);
            const int wb = warp * 72;
            #pragma unroll
            for (int j = lane; j < 72; j += 32)
                g4[wb + j] = s4o[wb + j];
        }

        q = qn; sv = svn;
        tile = next;
    }

    // ---- scalar tail (n % TPB points; none for N=8M) ----
    const int tail_base = ntiles_full * TPB;
    for (int i = tail_base + blockIdx.x * TPB + threadIdx.x; i < n;
         i += NBLOCKS * TPB) {
        const float4 qq = q_raw[i];
        const float n2 = qq.x * qq.x + qq.y * qq.y + qq.z * qq.z + qq.w * qq.w;
        const float inv = rsqrtf(fmaxf(n2, 1e-24f));
        const float w = qq.x * inv, x = qq.y * inv, y = qq.z * inv, z = qq.w * inv;
        const float sx = __expf(s_raw[3 * (size_t)i + 0]);
        const float sy = __expf(s_raw[3 * (size_t)i + 1]);
        const float sz = __expf(s_raw[3 * (size_t)i + 2]);

        const float m00 = (1.f - 2.f * (y * y + z * z)) * sx;
        const float m01 = (2.f * (x * y - w * z)) * sy;
        const float m02 = (2.f * (x * z + w * y)) * sz;
        const float m10 = (2.f * (x * y + w * z)) * sx;
        const float m11 = (1.f - 2.f * (x * x + z * z)) * sy;
        const float m12 = (2.f * (y * z - w * x)) * sz;
        const float m20 = (2.f * (x * z - w * y)) * sx;
        const float m21 = (2.f * (y * z + w * x)) * sy;
        const float m22 = (1.f - 2.f * (x * x + y * y)) * sz;

        float* o = out + 9 * (size_t)i;
        o[0] = m00 * m00 + m01 * m01 + m02 * m02;
        o[1] = m00 * m10 + m01 * m11 + m02 * m12;
        o[2] = m00 * m20 + m01 * m21 + m02 * m22;
        o[3] = o[1];
        o[4] = m10 * m10 + m11 * m11 + m12 * m12;
        o[5] = m10 * m20 + m11 * m21 + m12 * m22;
        o[6] = o[2];
        o[7] = o[5];
        o[8] = m20 * m20 + m21 * m21 + m22 * m22;
    }
}

extern "C" void kernel_launch(void* const* d_in, const int* in_sizes, int n_in,
                              void* d_out, int out_size)
{
    const float*  s_raw = (const float*)d_in[0];   // [N,3]
    const float4* q_raw = (const float4*)d_in[1];  // [N,4]
    float*        out   = (float*)d_out;           // [N,3,3]
    const int n = in_sizes[0] / 3;

    cov_kernel<<<NBLOCKS, TPB>>>(s_raw, q_raw, out, n);
}

// round 6
// speedup vs baseline: 1.1050x; 1.1050x over previous
#include <cuda_runtime.h>

#define TPB 256   // 8 warps; each warp owns a disjoint 32-point slice

// cov = R diag(s^2) R^T per point, s = exp(scaling_raw).
// scaling_raw [N,3] fp32, rotation_raw [N,4] fp32 (w,x,y,z), out [N,3,3] fp32.
__global__ __launch_bounds__(TPB) void cov_kernel(
    const float* __restrict__ s_raw,
    const float4* __restrict__ q_raw,
    float* __restrict__ out,
    int n)
{
    __shared__ float sh_o[TPB * 9];   // 9 KB per-warp-sliced output stage

    const int full_blocks = n / TPB;
    const int block_base  = blockIdx.x * TPB;
    const int warp = threadIdx.x >> 5;
    const int lane = threadIdx.x & 31;

    if (blockIdx.x < full_blocks) {
        const int i = block_base + threadIdx.x;

        // front-batch all loads: 1x LDG.128 + 3x LDG.32
        const float4 q = q_raw[i];
        const float s0 = s_raw[3 * (size_t)i + 0];
        const float s1 = s_raw[3 * (size_t)i + 1];
        const float s2 = s_raw[3 * (size_t)i + 2];

        const float n2 = q.x * q.x + q.y * q.y + q.z * q.z + q.w * q.w;
        const float inv = rsqrtf(fmaxf(n2, 1e-24f));
        const float w = q.x * inv, x = q.y * inv, y = q.z * inv, z = q.w * inv;

        // t_j = s_j^2 = exp(2*s_raw_j)
        const float tx = __expf(2.f * s0);
        const float ty = __expf(2.f * s1);
        const float tz = __expf(2.f * s2);

        // unit rotation matrix entries
        const float r00 = 1.f - 2.f * (y * y + z * z);
        const float r01 = 2.f * (x * y - w * z);
        const float r02 = 2.f * (x * z + w * y);
        const float r10 = 2.f * (x * y + w * z);
        const float r11 = 1.f - 2.f * (x * x + z * z);
        const float r12 = 2.f * (y * z - w * x);
        const float r20 = 2.f * (x * z - w * y);
        const float r21 = 2.f * (y * z + w * x);
        const float r22 = 1.f - 2.f * (x * x + y * y);

        // scale one factor: a_ij = r_ij * t_j
        const float a00 = r00 * tx, a01 = r01 * ty, a02 = r02 * tz;
        const float a10 = r10 * tx, a11 = r11 * ty, a12 = r12 * tz;
        const float a20 = r20 * tx, a21 = r21 * ty, a22 = r22 * tz;

        const float c00 = a00 * r00 + a01 * r01 + a02 * r02;
        const float c01 = a00 * r10 + a01 * r11 + a02 * r12;
        const float c02 = a00 * r20 + a01 * r21 + a02 * r22;
        const float c11 = a10 * r10 + a11 * r11 + a12 * r12;
        const float c12 = a10 * r20 + a11 * r21 + a12 * r22;
        const float c22 = a20 * r20 + a21 * r21 + a22 * r22;

        // stride-9 smem writes: gcd(9,32)=1 -> conflict-free
        float* o = &sh_o[threadIdx.x * 9];
        o[0] = c00; o[1] = c01; o[2] = c02;
        o[3] = c01; o[4] = c11; o[5] = c12;
        o[6] = c02; o[7] = c12; o[8] = c22;
        __syncwarp();

        // per-warp vectorized store: warp w owns float4 indices [w*72, w*72+72)
        {
            float4* g4 = reinterpret_cast<float4*>(out) +
                         (size_t)blockIdx.x * (TPB * 9 / 4);
            const float4* s4 = reinterpret_cast<const float4*>(sh_o);
            const int wb = warp * 72;
            #pragma unroll
            for (int j = lane; j < 72; j += 32)
                g4[wb + j] = s4[wb + j];
        }
    } else {
        // ---- scalar tail ----
        const int i = block_base + threadIdx.x;
        if (i >= n) return;
        const float4 q = q_raw[i];
        const float n2 = q.x * q.x + q.y * q.y + q.z * q.z + q.w * q.w;
        const float inv = rsqrtf(fmaxf(n2, 1e-24f));
        const float w = q.x * inv, x = q.y * inv, y = q.z * inv, z = q.w * inv;
        const float tx = __expf(2.f * s_raw[3 * (size_t)i + 0]);
        const float ty = __expf(2.f * s_raw[3 * (size_t)i + 1]);
        const float tz = __expf(2.f * s_raw[3 * (size_t)i + 2]);

        const float r00 = 1.f - 2.f * (y * y + z * z);
        const float r01 = 2.f * (x * y - w * z);
        const float r02 = 2.f * (x * z + w * y);
        const float r10 = 2.f * (x * y + w * z);
        const float r11 = 1.f - 2.f * (x * x + z * z);
        const float r12 = 2.f * (y * z - w * x);
        const float r20 = 2.f * (x * z - w * y);
        const float r21 = 2.f * (y * z + w * x);
        const float r22 = 1.f - 2.f * (x * x + y * y);

        const float a00 = r00 * tx, a01 = r01 * ty, a02 = r02 * tz;
        const float a10 = r10 * tx, a11 = r11 * ty, a12 = r12 * tz;
        const float a20 = r20 * tx, a21 = r21 * ty, a22 = r22 * tz;

        float* o = out + 9 * (size_t)i;
        o[0] = a00 * r00 + a01 * r01 + a02 * r02;
        o[1] = a00 * r10 + a01 * r11 + a02 * r12;
        o[2] = a00 * r20 + a01 * r21 + a02 * r22;
        o[3] = o[1];
        o[4] = a10 * r10 + a11 * r11 + a12 * r12;
        o[5] = a10 * r20 + a11 * r21 + a12 * r22;
        o[6] = o[2];
        o[7] = o[5];
        o[8] = a20 * r20 + a21 * r21 + a22 * r22;
    }
}

extern "C" void kernel_launch(void* const* d_in, const int* in_sizes, int n_in,
                              void* d_out, int out_size)
{
    const float*  s_raw = (const float*)d_in[0];   // [N,3]
    const float4* q_raw = (const float4*)d_in[1];  // [N,4]
    float*        out   = (float*)d_out;           // [N,3,3]
    const int n = in_sizes[0] / 3;

    const int blocks = (n + TPB - 1) / TPB;
    cov_kernel<<<blocks, TPB>>>(s_raw, q_raw, out, n);
}

// round 8
// speedup vs baseline: 1.1109x; 1.0053x over previous
#include <cuda_runtime.h>

#define TPB 256   // 8 warps; each warp owns a disjoint 32-point slice

// cov = R diag(s^2) R^T per point, s = exp(scaling_raw).
// scaling_raw [N,3] fp32, rotation_raw [N,4] fp32 (w,x,y,z), out [N,3,3] fp32.
__global__ __launch_bounds__(TPB) void cov_kernel(
    const float* __restrict__ s_raw,
    const float4* __restrict__ q_raw,
    float* __restrict__ out,
    int n)
{
    __shared__ float sh_s[TPB * 3];   // 3 KB per-warp-sliced scaling stage
    __shared__ float sh_o[TPB * 9];   // 9 KB per-warp-sliced output stage

    const int full_blocks = n / TPB;
    const int block_base  = blockIdx.x * TPB;
    const int warp = threadIdx.x >> 5;
    const int lane = threadIdx.x & 31;

    if (blockIdx.x < full_blocks) {
        // ---- per-warp scaling stage: warp w owns float4 indices [w*24, w*24+24) ----
        {
            const float4* g4 = reinterpret_cast<const float4*>(s_raw) +
                               (size_t)blockIdx.x * (TPB * 3 / 4);
            float4* s4 = reinterpret_cast<float4*>(sh_s);
            const int idx = warp * 24 + lane;
            if (lane < 24) s4[idx] = g4[idx];
        }

        const int i = block_base + threadIdx.x;
        const float4 q = q_raw[i];
        __syncwarp();

        const float n2 = q.x * q.x + q.y * q.y + q.z * q.z + q.w * q.w;
        const float inv = rsqrtf(fmaxf(n2, 1e-24f));
        const float w = q.x * inv, x = q.y * inv, y = q.z * inv, z = q.w * inv;

        // t_j = s_j^2 = exp(2*s_raw_j); scale only one GEMM factor
        const float tx = __expf(2.f * sh_s[threadIdx.x * 3 + 0]);
        const float ty = __expf(2.f * sh_s[threadIdx.x * 3 + 1]);
        const float tz = __expf(2.f * sh_s[threadIdx.x * 3 + 2]);

        const float r00 = 1.f - 2.f * (y * y + z * z);
        const float r01 = 2.f * (x * y - w * z);
        const float r02 = 2.f * (x * z + w * y);
        const float r10 = 2.f * (x * y + w * z);
        const float r11 = 1.f - 2.f * (x * x + z * z);
        const float r12 = 2.f * (y * z - w * x);
        const float r20 = 2.f * (x * z - w * y);
        const float r21 = 2.f * (y * z + w * x);
        const float r22 = 1.f - 2.f * (x * x + y * y);

        const float a00 = r00 * tx, a01 = r01 * ty, a02 = r02 * tz;
        const float a10 = r10 * tx, a11 = r11 * ty, a12 = r12 * tz;
        const float a20 = r20 * tx, a21 = r21 * ty, a22 = r22 * tz;

        const float c00 = a00 * r00 + a01 * r01 + a02 * r02;
        const float c01 = a00 * r10 + a01 * r11 + a02 * r12;
        const float c02 = a00 * r20 + a01 * r21 + a02 * r22;
        const float c11 = a10 * r10 + a11 * r11 + a12 * r12;
        const float c12 = a10 * r20 + a11 * r21 + a12 * r22;
        const float c22 = a20 * r20 + a21 * r21 + a22 * r22;

        // stride-9 smem writes: gcd(9,32)=1 -> conflict-free
        float* o = &sh_o[threadIdx.x * 9];
        o[0] = c00; o[1] = c01; o[2] = c02;
        o[3] = c01; o[4] = c11; o[5] = c12;
        o[6] = c02; o[7] = c12; o[8] = c22;
        __syncwarp();

        // ---- per-warp vectorized store: warp w owns float4 indices [w*72, w*72+72) ----
        {
            float4* g4 = reinterpret_cast<float4*>(out) +
                         (size_t)blockIdx.x * (TPB * 9 / 4);
            const float4* s4 = reinterpret_cast<const float4*>(sh_o);
            const int wb = warp * 72;
            #pragma unroll
            for (int j = lane; j < 72; j += 32)
                g4[wb + j] = s4[wb + j];
        }
    } else {
        // ---- scalar tail ----
        const int i = block_base + threadIdx.x;
        if (i >= n) return;
        const float4 q = q_raw[i];
        const float n2 = q.x * q.x + q.y * q.y + q.z * q.z + q.w * q.w;
        const float inv = rsqrtf(fmaxf(n2, 1e-24f));
        const float w = q.x * inv, x = q.y * inv, y = q.z * inv, z = q.w * inv;
        const float tx = __expf(2.f * s_raw[3 * (size_t)i + 0]);
        const float ty = __expf(2.f * s_raw[3 * (size_t)i + 1]);
        const float tz = __expf(2.f * s_raw[3 * (size_t)i + 2]);

        const float r00 = 1.f - 2.f * (y * y + z * z);
        const float r01 = 2.f * (x * y - w * z);
        const float r02 = 2.f * (x * z + w * y);
        const float r10 = 2.f * (x * y + w * z);
        const float r11 = 1.f - 2.f * (x * x + z * z);
        const float r12 = 2.f * (y * z - w * x);
        const float r20 = 2.f * (x * z - w * y);
        const float r21 = 2.f * (y * z + w * x);
        const float r22 = 1.f - 2.f * (x * x + y * y);

        const float a00 = r00 * tx, a01 = r01 * ty, a02 = r02 * tz;
        const float a10 = r10 * tx, a11 = r11 * ty, a12 = r12 * tz;
        const float a20 = r20 * tx, a21 = r21 * ty, a22 = r22 * tz;

        float* o = out + 9 * (size_t)i;
        o[0] = a00 * r00 + a01 * r01 + a02 * r02;
        o[1] = a00 * r10 + a01 * r11 + a02 * r12;
        o[2] = a00 * r20 + a01 * r21 + a02 * r22;
        o[3] = o[1];
        o[4] = a10 * r10 + a11 * r11 + a12 * r12;
        o[5] = a10 * r20 + a11 * r21 + a12 * r22;
        o[6] = o[2];
        o[7] = o[5];
        o[8] = a20 * r20 + a21 * r21 + a22 * r22;
    }
}

extern "C" void kernel_launch(void* const* d_in, const int* in_sizes, int n_in,
                              void* d_out, int out_size)
{
    const float*  s_raw = (const float*)d_in[0];   // [N,3]
    const float4* q_raw = (const float4*)d_in[1];  // [N,4]
    float*        out   = (float*)d_out;           // [N,3,3]
    const int n = in_sizes[0] / 3;

    const int blocks = (n + TPB - 1) / TPB;
    cov_kernel<<<blocks, TPB>>>(s_raw, q_raw, out, n);
}